// round 12
// baseline (speedup 1.0000x reference)
#include <cuda_runtime.h>
#include <cstdint>

// Problem constants (fixed by the dataset)
#define NN 100000
#define NE 1600000
#define F  64
#define SLOTS 96   // per-node adjacency bin; Poisson(16) in-degree => P(deg>96) ~ 0

#define TILE_M 128 // nodes per block in layer kernel
#define KDIM   128 // concat K (64 self + 64 neigh)

typedef unsigned long long ULL;

// Scratch: __device__ globals (no allocations allowed anywhere)
__device__ float g_agg1[(size_t)NN * F];
__device__ float g_agg2[(size_t)NN * F];
__device__ float g_h[(size_t)NN * F];
__device__ int   g_adj[(size_t)NN * SLOTS];
__device__ int   g_cnt[NN];

// ---------------- packed f32x2 helpers (Blackwell) ----------------
__device__ __forceinline__ ULL ffma2(ULL a, ULL b, ULL c) {
    ULL d;
    asm("fma.rn.f32x2 %0, %1, %2, %3;" : "=l"(d) : "l"(a), "l"(b), "l"(c));
    return d;
}
__device__ __forceinline__ ULL pack2(float x) {
    ULL d;
    unsigned u = __float_as_uint(x);
    asm("mov.b64 %0, {%1, %1};" : "=l"(d) : "r"(u));
    return d;
}
__device__ __forceinline__ void unpack2(ULL v, float& lo, float& hi) {
    unsigned a, b;
    asm("mov.b64 {%0, %1}, %2;" : "=r"(a), "=r"(b) : "l"(v));
    lo = __uint_as_float(a);
    hi = __uint_as_float(b);
}

// ---------------------------------------------------------------------------
// Zero per-node cursors (fresh every launch; graph replays)
// ---------------------------------------------------------------------------
__global__ void zero_cnt_kernel() {
    int i = blockIdx.x * blockDim.x + threadIdx.x;
    if (i < NN) g_cnt[i] = 0;
}

// ---------------------------------------------------------------------------
// Build per-dst adjacency bins: g_adj[d*SLOTS + k] = k-th in-neighbor of d
// ---------------------------------------------------------------------------
__global__ void scatter_kernel(const int* __restrict__ src,
                               const int* __restrict__ dst, int e) {
    int i = blockIdx.x * blockDim.x + threadIdx.x;
    if (i >= e) return;
    int d = dst[i];
    int pos = atomicAdd(&g_cnt[d], 1);
    if (pos < SLOTS) g_adj[(size_t)d * SLOTS + pos] = src[i];
}

// ---------------------------------------------------------------------------
// Gather-form mean aggregation: one warp per node (near the L2 roofline)
// ---------------------------------------------------------------------------
__global__ void agg_csr_kernel(const float* __restrict__ x, int layer) {
    int warp = (blockIdx.x * blockDim.x + threadIdx.x) >> 5;
    int lane = threadIdx.x & 31;
    if (warp >= NN) return;

    const float* feat = (layer == 1) ? x : g_h;
    float* aggout     = (layer == 1) ? g_agg1 : g_agg2;

    int deg_full = g_cnt[warp];
    int deg = (deg_full < SLOTS) ? deg_full : SLOTS;
    const int* adj = g_adj + (size_t)warp * SLOTS;

    int half = lane >> 4;
    int fl   = lane & 15;

    float4 acc0 = make_float4(0.f, 0.f, 0.f, 0.f);
    float4 acc1 = make_float4(0.f, 0.f, 0.f, 0.f);

    for (int base = 0; base < deg; base += 32) {
        int cnt = deg - base;
        if (cnt > 32) cnt = 32;
        int idx = (lane < cnt) ? adj[base + lane] : 0;
        for (int j = 0; j < cnt; j += 4) {
            int sl0 = j + half;     if (sl0 > cnt - 1) sl0 = cnt - 1;
            int sl1 = j + 2 + half; if (sl1 > cnt - 1) sl1 = cnt - 1;
            int s0 = __shfl_sync(0xffffffffu, idx, sl0);
            int s1 = __shfl_sync(0xffffffffu, idx, sl1);
            float4 v0 = *reinterpret_cast<const float4*>(feat + (size_t)s0 * F + fl * 4);
            float4 v1 = *reinterpret_cast<const float4*>(feat + (size_t)s1 * F + fl * 4);
            if (j + half < cnt) {
                acc0.x += v0.x; acc0.y += v0.y; acc0.z += v0.z; acc0.w += v0.w;
            }
            if (j + 2 + half < cnt) {
                acc1.x += v1.x; acc1.y += v1.y; acc1.z += v1.z; acc1.w += v1.w;
            }
        }
    }
    acc0.x += acc1.x; acc0.y += acc1.y; acc0.z += acc1.z; acc0.w += acc1.w;

    acc0.x += __shfl_xor_sync(0xffffffffu, acc0.x, 16);
    acc0.y += __shfl_xor_sync(0xffffffffu, acc0.y, 16);
    acc0.z += __shfl_xor_sync(0xffffffffu, acc0.z, 16);
    acc0.w += __shfl_xor_sync(0xffffffffu, acc0.w, 16);

    if (half == 0) {
        float inv = (deg_full > 0) ? (1.0f / (float)deg_full) : 0.0f;
        float4 r = make_float4(acc0.x * inv, acc0.y * inv, acc0.z * inv, acc0.w * inv);
        *reinterpret_cast<float4*>(aggout + (size_t)warp * F + fl * 4) = r;
    }
}

// ---------------------------------------------------------------------------
// Fused SAGE layer:  out = act([in|agg] @ [Ws;Wn] + b)
// Block = 256 threads -> 128-node x 64-output tile.
// Thread = 4 nodes x 8 outputs (og = tid&7, ng = tid>>3 in 0..31).
//
// A read directly from global (L2-resident; HW dedups the 8 og-threads'
// identical addresses), 1-deep prefetch pipeline overlaps the loads with
// the 64-FFMA2 block. W (chunk-permuted, conflict-free) + bias in smem.
// Smaller thread tile than R11 -> ~115 regs -> 2 blocks x 8 warps = 16
// warps/SM (2x R11) to cover the residual latency.
// ---------------------------------------------------------------------------
__global__ void __launch_bounds__(256, 2)
layer_kernel(const float* __restrict__ x,
             const float* __restrict__ Ws,
             const float* __restrict__ Wn,
             const float* __restrict__ bias,
             float* __restrict__ dout,
             int n, int layer) {
    __shared__ float sW[KDIM * 64];   // rows 0..63 = Ws, 64..127 = Wn, chunk-permuted
    __shared__ float sb[64];

    const float* in  = (layer == 1) ? x : g_h;
    const float* agg = (layer == 1) ? g_agg1 : g_agg2;  // pre-scaled by 1/deg
    float* out       = (layer == 1) ? g_h : dout;

    int tid = threadIdx.x;
    int node0 = blockIdx.x * TILE_M;

    // Stage weights with chunk permutation pc = (c&1)*8 + (c>>1):
    // warp's 8 og-chunks for each 16B read span all 32 banks once.
    {
        const float4* Ws4 = reinterpret_cast<const float4*>(Ws);
        const float4* Wn4 = reinterpret_cast<const float4*>(Wn);
        float4* sW4 = reinterpret_cast<float4*>(sW);
        for (int i = tid; i < 64 * 16; i += 256) {
            int r = i >> 4, c = i & 15;
            int pc = ((c & 1) << 3) | (c >> 1);
            sW4[r * 16 + pc] = Ws4[i];
            sW4[(64 + r) * 16 + pc] = Wn4[i];
        }
        if (tid < 16)
            reinterpret_cast<float4*>(sb)[tid] =
                reinterpret_cast<const float4*>(bias)[tid];
    }
    __syncthreads();

    const int og = tid & 7;   // outputs og*8 .. og*8+7
    const int ng = tid >> 3;  // nodes   ng*4 .. ng*4+3

    // Clamped per-node row pointers (ragged last block reads row n-1)
    const float4* pin[4];
    const float4* pagg[4];
#pragma unroll
    for (int i = 0; i < 4; i++) {
        int node = node0 + ng * 4 + i;
        if (node > n - 1) node = n - 1;
        pin[i]  = reinterpret_cast<const float4*>(in  + (size_t)node * F);
        pagg[i] = reinterpret_cast<const float4*>(agg + (size_t)node * F);
    }

    ULL acc[16];              // [4 nodes][4 output-pairs]
    {
        const ULL* sb2 = reinterpret_cast<const ULL*>(sb);
        ULL b0 = sb2[og * 4 + 0], b1 = sb2[og * 4 + 1];
        ULL b2 = sb2[og * 4 + 2], b3 = sb2[og * 4 + 3];
#pragma unroll
        for (int i = 0; i < 4; i++) {
            acc[i * 4 + 0] = b0; acc[i * 4 + 1] = b1;
            acc[i * 4 + 2] = b2; acc[i * 4 + 3] = b3;
        }
    }

    float4 a_cur[4], a_nxt[4];
#pragma unroll
    for (int i = 0; i < 4; i++) a_cur[i] = __ldg(pin[i]);

    // FMA step for 4 K-rows starting at WBASE + K4*4 against a_cur
#define FMA_STEP(WBASE, K4)                                                    \
    {                                                                          \
        ULL w_[4][4];                                                          \
        _Pragma("unroll")                                                      \
        for (int kk = 0; kk < 4; kk++) {                                       \
            const float* wrow = sW + ((WBASE) + (K4) * 4 + kk) * 64;           \
            ulonglong2 u0 = *reinterpret_cast<const ulonglong2*>(wrow + og * 4);\
            ulonglong2 u1 = *reinterpret_cast<const ulonglong2*>(wrow + 32 + og * 4);\
            w_[kk][0] = u0.x; w_[kk][1] = u0.y;                                \
            w_[kk][2] = u1.x; w_[kk][3] = u1.y;                                \
        }                                                                      \
        _Pragma("unroll")                                                      \
        for (int i = 0; i < 4; i++) {                                          \
            float as[4] = {a_cur[i].x, a_cur[i].y, a_cur[i].z, a_cur[i].w};    \
            _Pragma("unroll")                                                  \
            for (int kk = 0; kk < 4; kk++) {                                   \
                ULL av = pack2(as[kk]);                                        \
                acc[i * 4 + 0] = ffma2(av, w_[kk][0], acc[i * 4 + 0]);         \
                acc[i * 4 + 1] = ffma2(av, w_[kk][1], acc[i * 4 + 1]);         \
                acc[i * 4 + 2] = ffma2(av, w_[kk][2], acc[i * 4 + 2]);         \
                acc[i * 4 + 3] = ffma2(av, w_[kk][3], acc[i * 4 + 3]);         \
            }                                                                  \
        }                                                                      \
    }

    // Half 1: K 0..63 from `in` (sW rows 0..63)
#pragma unroll
    for (int k4 = 0; k4 < 16; k4++) {
        if (k4 < 15) {
#pragma unroll
            for (int i = 0; i < 4; i++) a_nxt[i] = __ldg(pin[i] + k4 + 1);
        } else {
#pragma unroll
            for (int i = 0; i < 4; i++) a_nxt[i] = __ldg(pagg[i]);
        }
        FMA_STEP(0, k4);
#pragma unroll
        for (int i = 0; i < 4; i++) a_cur[i] = a_nxt[i];
    }

    // Half 2: K 64..127 from `agg` (sW rows 64..127)
#pragma unroll
    for (int k4 = 0; k4 < 16; k4++) {
        if (k4 < 15) {
#pragma unroll
            for (int i = 0; i < 4; i++) a_nxt[i] = __ldg(pagg[i] + k4 + 1);
        }
        FMA_STEP(64, k4);
#pragma unroll
        for (int i = 0; i < 4; i++) a_cur[i] = a_nxt[i];
    }
#undef FMA_STEP

    // Store 4 nodes x 8 outputs
#pragma unroll
    for (int i = 0; i < 4; i++) {
        int node = node0 + ng * 4 + i;
        if (node >= n) break;
        float o[8];
#pragma unroll
        for (int p = 0; p < 4; p++) unpack2(acc[i * 4 + p], o[p * 2], o[p * 2 + 1]);
        if (layer == 1) {
#pragma unroll
            for (int j = 0; j < 8; j++) o[j] = fmaxf(o[j], 0.0f);
        }
        float4* orow = reinterpret_cast<float4*>(out + (size_t)node * F + og * 8);
        orow[0] = make_float4(o[0], o[1], o[2], o[3]);
        orow[1] = make_float4(o[4], o[5], o[6], o[7]);
    }
}

// ---------------------------------------------------------------------------
// kernel_launch
// Inputs (metadata order): x, src, dst, W_self1, W_neigh1, b1, W_self2,
//                          W_neigh2, b2   (src/dst are int32)
// ---------------------------------------------------------------------------
extern "C" void kernel_launch(void* const* d_in, const int* in_sizes, int n_in,
                              void* d_out, int out_size) {
    const float* x   = (const float*)d_in[0];
    const int*   src = (const int*)d_in[1];
    const int*   dst = (const int*)d_in[2];
    const float* Ws1 = (const float*)d_in[3];
    const float* Wn1 = (const float*)d_in[4];
    const float* b1  = (const float*)d_in[5];
    const float* Ws2 = (const float*)d_in[6];
    const float* Wn2 = (const float*)d_in[7];
    const float* b2  = (const float*)d_in[8];
    float* out = (float*)d_out;

    const int N = in_sizes[0] / F;   // 100000
    const int E = in_sizes[1];       // 1600000
    const int nblk = (N + TILE_M - 1) / TILE_M;

    // 1) Build adjacency bins (shared by both layers)
    zero_cnt_kernel<<<(NN + 255) / 256, 256>>>();
    scatter_kernel<<<(E + 255) / 256, 256>>>(src, dst, E);

    // 2) Layer 1 aggregation (gather-only, mean folded in) -> g_agg1
    {
        long long threads = (long long)NN * 32;
        int blocks = (int)((threads + 255) / 256);
        agg_csr_kernel<<<blocks, 256>>>(x, 1);
    }

    // 3) Layer 1 GEMM + ReLU -> g_h
    layer_kernel<<<nblk, 256>>>(x, Ws1, Wn1, b1, out, N, 1);

    // 4) Layer 2 aggregation -> g_agg2
    {
        long long threads = (long long)NN * 32;
        int blocks = (int)((threads + 255) / 256);
        agg_csr_kernel<<<blocks, 256>>>(x, 2);
    }

    // 5) Layer 2 GEMM -> d_out
    layer_kernel<<<nblk, 256>>>(x, Ws2, Wn2, b2, out, N, 2);
}

// round 16
// speedup vs baseline: 1.0674x; 1.0674x over previous
#include <cuda_runtime.h>
#include <cstdint>

// Problem constants (fixed by the dataset)
#define NN 100000
#define NE 1600000
#define F  64
#define SLOTS 96   // per-node adjacency bin; Poisson(16) in-degree => P(deg>96) ~ 0

#define TILE_M 128 // nodes per block in layer kernel
#define KDIM   128 // concat K (64 self + 64 neigh)
#define DEPTH  4   // cp.async pipeline depth (chunks in flight)

typedef unsigned long long ULL;

// Scratch: __device__ globals (no allocations allowed anywhere)
__device__ float g_agg1[(size_t)NN * F];
__device__ float g_agg2[(size_t)NN * F];
__device__ float g_h[(size_t)NN * F];
__device__ int   g_adj[(size_t)NN * SLOTS];
__device__ int   g_cnt[NN];

// ---------------- packed f32x2 helpers (Blackwell) ----------------
__device__ __forceinline__ ULL ffma2(ULL a, ULL b, ULL c) {
    ULL d;
    asm("fma.rn.f32x2 %0, %1, %2, %3;" : "=l"(d) : "l"(a), "l"(b), "l"(c));
    return d;
}
__device__ __forceinline__ ULL pack2(float x) {
    ULL d;
    unsigned u = __float_as_uint(x);
    asm("mov.b64 %0, {%1, %1};" : "=l"(d) : "r"(u));
    return d;
}
__device__ __forceinline__ void unpack2(ULL v, float& lo, float& hi) {
    unsigned a, b;
    asm("mov.b64 {%0, %1}, %2;" : "=r"(a), "=r"(b) : "l"(v));
    lo = __uint_as_float(a);
    hi = __uint_as_float(b);
}
__device__ __forceinline__ uint32_t smem_u32(const void* p) {
    uint32_t a;
    asm("{ .reg .u64 t; cvta.to.shared.u64 t, %1; cvt.u32.u64 %0, t; }"
        : "=r"(a) : "l"(p));
    return a;
}

// ---------------------------------------------------------------------------
// Zero per-node cursors (fresh every launch; graph replays)
// ---------------------------------------------------------------------------
__global__ void zero_cnt_kernel() {
    int i = blockIdx.x * blockDim.x + threadIdx.x;
    if (i < NN) g_cnt[i] = 0;
}

// ---------------------------------------------------------------------------
// Build per-dst adjacency bins: g_adj[d*SLOTS + k] = k-th in-neighbor of d
// ---------------------------------------------------------------------------
__global__ void scatter_kernel(const int* __restrict__ src,
                               const int* __restrict__ dst, int e) {
    int i = blockIdx.x * blockDim.x + threadIdx.x;
    if (i >= e) return;
    int d = dst[i];
    int pos = atomicAdd(&g_cnt[d], 1);
    if (pos < SLOTS) g_adj[(size_t)d * SLOTS + pos] = src[i];
}

// ---------------------------------------------------------------------------
// Gather-form mean aggregation: one warp per node (near the L2 roofline)
// ---------------------------------------------------------------------------
__global__ void agg_csr_kernel(const float* __restrict__ x, int layer) {
    int warp = (blockIdx.x * blockDim.x + threadIdx.x) >> 5;
    int lane = threadIdx.x & 31;
    if (warp >= NN) return;

    const float* feat = (layer == 1) ? x : g_h;
    float* aggout     = (layer == 1) ? g_agg1 : g_agg2;

    int deg_full = g_cnt[warp];
    int deg = (deg_full < SLOTS) ? deg_full : SLOTS;
    const int* adj = g_adj + (size_t)warp * SLOTS;

    int half = lane >> 4;
    int fl   = lane & 15;

    float4 acc0 = make_float4(0.f, 0.f, 0.f, 0.f);
    float4 acc1 = make_float4(0.f, 0.f, 0.f, 0.f);

    for (int base = 0; base < deg; base += 32) {
        int cnt = deg - base;
        if (cnt > 32) cnt = 32;
        int idx = (lane < cnt) ? adj[base + lane] : 0;
        for (int j = 0; j < cnt; j += 4) {
            int sl0 = j + half;     if (sl0 > cnt - 1) sl0 = cnt - 1;
            int sl1 = j + 2 + half; if (sl1 > cnt - 1) sl1 = cnt - 1;
            int s0 = __shfl_sync(0xffffffffu, idx, sl0);
            int s1 = __shfl_sync(0xffffffffu, idx, sl1);
            float4 v0 = *reinterpret_cast<const float4*>(feat + (size_t)s0 * F + fl * 4);
            float4 v1 = *reinterpret_cast<const float4*>(feat + (size_t)s1 * F + fl * 4);
            if (j + half < cnt) {
                acc0.x += v0.x; acc0.y += v0.y; acc0.z += v0.z; acc0.w += v0.w;
            }
            if (j + 2 + half < cnt) {
                acc1.x += v1.x; acc1.y += v1.y; acc1.z += v1.z; acc1.w += v1.w;
            }
        }
    }
    acc0.x += acc1.x; acc0.y += acc1.y; acc0.z += acc1.z; acc0.w += acc1.w;

    acc0.x += __shfl_xor_sync(0xffffffffu, acc0.x, 16);
    acc0.y += __shfl_xor_sync(0xffffffffu, acc0.y, 16);
    acc0.z += __shfl_xor_sync(0xffffffffu, acc0.z, 16);
    acc0.w += __shfl_xor_sync(0xffffffffu, acc0.w, 16);

    if (half == 0) {
        float inv = (deg_full > 0) ? (1.0f / (float)deg_full) : 0.0f;
        float4 r = make_float4(acc0.x * inv, acc0.y * inv, acc0.z * inv, acc0.w * inv);
        *reinterpret_cast<float4*>(aggout + (size_t)warp * F + fl * 4) = r;
    }
}

// ---------------------------------------------------------------------------
// Fused SAGE layer:  out = act([in|agg] @ [Ws;Wn] + b)
// Block = 128 threads (4 warps) -> 128-node x 64-output tile.
// Thread = 8 nodes x 8 outputs (og = tid&7, ng = tid>>3).
//
// A pipeline: each warp owns its 32 A-rows. Per k4-chunk, ONE cp.async.cg
// (16B/lane) stages 512B into a per-warp smem slot (DEPTH=4 in flight ->
// ~1000 cycles of DRAM-latency cover, zero register cost). Slot layout is
// transposed (addr = ((r&7)*4 + (r>>3))*16B) so the consumer LDS.128 is
// single-phase. Only warp-local sync (wait_group + syncwarp) — no barrier.
// W (chunk-permuted, conflict-free) + bias in smem as before.
// ---------------------------------------------------------------------------
__global__ void __launch_bounds__(128, 3)
layer_kernel(const float* __restrict__ x,
             const float* __restrict__ Ws,
             const float* __restrict__ Wn,
             const float* __restrict__ bias,
             float* __restrict__ dout,
             int n, int layer) {
    __shared__ float sW[KDIM * 64];            // rows 0..63 = Ws, 64..127 = Wn
    __shared__ float sb[64];
    __shared__ float sA[4][DEPTH][128];        // [warp][slot][32 rows x 4 floats]

    const float* in  = (layer == 1) ? x : g_h;
    const float* agg = (layer == 1) ? g_agg1 : g_agg2;  // pre-scaled by 1/deg
    float* out       = (layer == 1) ? g_h : dout;

    int tid = threadIdx.x;
    int node0 = blockIdx.x * TILE_M;

    // Stage weights with chunk permutation pc = (c&1)*8 + (c>>1):
    // warp's 8 og-chunks for each 16B read span all 32 banks once.
    {
        const float4* Ws4 = reinterpret_cast<const float4*>(Ws);
        const float4* Wn4 = reinterpret_cast<const float4*>(Wn);
        float4* sW4 = reinterpret_cast<float4*>(sW);
        for (int i = tid; i < 64 * 16; i += 128) {
            int r = i >> 4, c = i & 15;
            int pc = ((c & 1) << 3) | (c >> 1);
            sW4[r * 16 + pc] = Ws4[i];
            sW4[(64 + r) * 16 + pc] = Wn4[i];
        }
        if (tid < 16)
            reinterpret_cast<float4*>(sb)[tid] =
                reinterpret_cast<const float4*>(bias)[tid];
    }
    __syncthreads();

    const int og   = tid & 7;          // outputs og*8 .. og*8+7
    const int ng   = tid >> 3;         // nodes   ng*8 .. ng*8+7
    const int warp = tid >> 5;
    const int lane = tid & 31;
    const int ngl  = ng & 3;           // ng within warp

    // This lane's cp.async duty: global row node0 + warp*32 + lane (clamped)
    int grow = node0 + warp * 32 + lane;
    if (grow > n - 1) grow = n - 1;
    const float4* gin  = reinterpret_cast<const float4*>(in  + (size_t)grow * F);
    const float4* gagg = reinterpret_cast<const float4*>(agg + (size_t)grow * F);

    // smem write address for this lane (transposed slot layout)
    uint32_t sdst0 = smem_u32(&sA[warp][0][0]) +
                     (uint32_t)(((lane & 7) * 4 + (lane >> 3)) * 16);

#define ISSUE_CHUNK(C)                                                         \
    {                                                                          \
        const float4* gp = ((C) < 16) ? (gin + (C)) : (gagg + ((C) - 16));     \
        uint32_t sd = sdst0 + (uint32_t)(((C) & (DEPTH - 1)) * 512);           \
        asm volatile("cp.async.cg.shared.global [%0], [%1], 16;"               \
                     :: "r"(sd), "l"(gp) : "memory");                          \
        asm volatile("cp.async.commit_group;" ::: "memory");                   \
    }

    // Prologue: fill the pipeline
#pragma unroll
    for (int c = 0; c < DEPTH; c++) ISSUE_CHUNK(c);

    ULL acc[32];              // [8 nodes][4 output-pairs]
    {
        const ULL* sb2 = reinterpret_cast<const ULL*>(sb);
        ULL b0 = sb2[og * 4 + 0], b1 = sb2[og * 4 + 1];
        ULL b2 = sb2[og * 4 + 2], b3 = sb2[og * 4 + 3];
#pragma unroll
        for (int i = 0; i < 8; i++) {
            acc[i * 4 + 0] = b0; acc[i * 4 + 1] = b1;
            acc[i * 4 + 2] = b2; acc[i * 4 + 3] = b3;
        }
    }

    const float* aslot_base = &sA[warp][0][0];

#pragma unroll
    for (int c4 = 0; c4 < 32; c4++) {
        asm volatile("cp.async.wait_group %0;" :: "n"(DEPTH - 1) : "memory");
        __syncwarp();

        // Read this chunk's 8 A values (rows ngl*8+i at addr (i*4+ngl)*16B)
        const float4* aslot = reinterpret_cast<const float4*>(
            aslot_base + (c4 & (DEPTH - 1)) * 128);
        float4 a_[8];
#pragma unroll
        for (int i = 0; i < 8; i++) a_[i] = aslot[i * 4 + ngl];

        // Refill the slot we just consumed (timing-safe: the cp.async's
        // global fetch lands >>100 cycles after the LDS above issued)
        if (c4 + DEPTH < 32) ISSUE_CHUNK(c4 + DEPTH);

        // W rows c4*4 .. c4*4+3 (spans Ws then Wn halves as c4 grows)
        ULL w_[4][4];
#pragma unroll
        for (int kk = 0; kk < 4; kk++) {
            const float* wrow = sW + (c4 * 4 + kk) * 64;
            ulonglong2 u0 = *reinterpret_cast<const ulonglong2*>(wrow + og * 4);
            ulonglong2 u1 = *reinterpret_cast<const ulonglong2*>(wrow + 32 + og * 4);
            w_[kk][0] = u0.x; w_[kk][1] = u0.y;
            w_[kk][2] = u1.x; w_[kk][3] = u1.y;
        }

#pragma unroll
        for (int i = 0; i < 8; i++) {
            float as[4] = {a_[i].x, a_[i].y, a_[i].z, a_[i].w};
#pragma unroll
            for (int kk = 0; kk < 4; kk++) {
                ULL av = pack2(as[kk]);
                acc[i * 4 + 0] = ffma2(av, w_[kk][0], acc[i * 4 + 0]);
                acc[i * 4 + 1] = ffma2(av, w_[kk][1], acc[i * 4 + 1]);
                acc[i * 4 + 2] = ffma2(av, w_[kk][2], acc[i * 4 + 2]);
                acc[i * 4 + 3] = ffma2(av, w_[kk][3], acc[i * 4 + 3]);
            }
        }
    }
#undef ISSUE_CHUNK

    // Store 8 nodes x 8 outputs
#pragma unroll
    for (int i = 0; i < 8; i++) {
        int node = node0 + ng * 8 + i;
        if (node >= n) break;
        float o[8];
#pragma unroll
        for (int p = 0; p < 4; p++) unpack2(acc[i * 4 + p], o[p * 2], o[p * 2 + 1]);
        if (layer == 1) {
#pragma unroll
            for (int j = 0; j < 8; j++) o[j] = fmaxf(o[j], 0.0f);
        }
        float4* orow = reinterpret_cast<float4*>(out + (size_t)node * F + og * 8);
        orow[0] = make_float4(o[0], o[1], o[2], o[3]);
        orow[1] = make_float4(o[4], o[5], o[6], o[7]);
    }
}

// ---------------------------------------------------------------------------
// kernel_launch
// Inputs (metadata order): x, src, dst, W_self1, W_neigh1, b1, W_self2,
//                          W_neigh2, b2   (src/dst are int32)
// ---------------------------------------------------------------------------
extern "C" void kernel_launch(void* const* d_in, const int* in_sizes, int n_in,
                              void* d_out, int out_size) {
    const float* x   = (const float*)d_in[0];
    const int*   src = (const int*)d_in[1];
    const int*   dst = (const int*)d_in[2];
    const float* Ws1 = (const float*)d_in[3];
    const float* Wn1 = (const float*)d_in[4];
    const float* b1  = (const float*)d_in[5];
    const float* Ws2 = (const float*)d_in[6];
    const float* Wn2 = (const float*)d_in[7];
    const float* b2  = (const float*)d_in[8];
    float* out = (float*)d_out;

    const int N = in_sizes[0] / F;   // 100000
    const int E = in_sizes[1];       // 1600000
    const int nblk = (N + TILE_M - 1) / TILE_M;

    // 1) Build adjacency bins (shared by both layers)
    zero_cnt_kernel<<<(NN + 255) / 256, 256>>>();
    scatter_kernel<<<(E + 255) / 256, 256>>>(src, dst, E);

    // 2) Layer 1 aggregation (gather-only, mean folded in) -> g_agg1
    {
        long long threads = (long long)NN * 32;
        int blocks = (int)((threads + 255) / 256);
        agg_csr_kernel<<<blocks, 256>>>(x, 1);
    }

    // 3) Layer 1 GEMM + ReLU -> g_h
    layer_kernel<<<nblk, 128>>>(x, Ws1, Wn1, b1, out, N, 1);

    // 4) Layer 2 aggregation -> g_agg2
    {
        long long threads = (long long)NN * 32;
        int blocks = (int)((threads + 255) / 256);
        agg_csr_kernel<<<blocks, 256>>>(x, 2);
    }

    // 5) Layer 2 GEMM -> d_out
    layer_kernel<<<nblk, 128>>>(x, Ws2, Wn2, b2, out, N, 2);
}